// round 4
// baseline (speedup 1.0000x reference)
#include <cuda_runtime.h>
#include <math.h>

// TimeLSTM: B=256, S=512, D=64, H=128
#define BB 256
#define SS 512
#define DD 64
#define HH 128
#define GG (5*HH)   // 640
#define NROWS (BB*SS)

__device__ float g_pre[(size_t)BB * SS * GG];

typedef unsigned long long ull;

__device__ __forceinline__ float sigm(float x) { return 1.0f / (1.0f + __expf(-x)); }
__device__ __forceinline__ float tanh_fast(float x) {
    float s = 1.0f / (1.0f + __expf(-2.0f * x));
    return fmaf(2.0f, s, -1.0f);
}
__device__ __forceinline__ ull pack2(float lo, float hi) {
    return ((ull)__float_as_uint(hi) << 32) | (ull)__float_as_uint(lo);
}
__device__ __forceinline__ float lo2(ull v) { return __uint_as_float((unsigned)v); }
__device__ __forceinline__ float hi2(ull v) { return __uint_as_float((unsigned)(v >> 32)); }

#define FMA2(d,a,b,c) asm("fma.rn.f32x2 %0, %1, %2, %3;" : "=l"(d) : "l"(a), "l"(b), "l"(c))

__device__ __forceinline__ void cp_async16(void* smem, const void* gmem) {
    unsigned saddr = (unsigned)__cvta_generic_to_shared(smem);
    asm volatile("cp.async.ca.shared.global [%0], [%1], 16;" :: "r"(saddr), "l"(gmem));
}
#define CP_COMMIT() asm volatile("cp.async.commit_group;")

// ---------------------------------------------------------------------------
// Kernel A: pre-activations. Wx column lives in registers (32 f32x2 pairs per
// thread); x rows stream via cp.async double buffer + broadcast LDS.
// 148 blocks x 640 threads, ~886 rows/block, 8-row tiles, 2-row ILP.
// ---------------------------------------------------------------------------
#define RT 8
#define PREGRID 148
__global__ __launch_bounds__(640, 1) void pre_kernel(
    const float* __restrict__ x, const float* __restrict__ td,
    const float* __restrict__ Wx, const float* __restrict__ wt1,
    const float* __restrict__ wt, const float* __restrict__ bias)
{
    __shared__ __align__(16) float xs[2][RT * DD];
    __shared__ float tds[2][RT];

    const int col = threadIdx.x;          // 0..639
    // Wx[:,col] as packed pairs (coalesced across col per k)
    ull w[DD / 2];
    #pragma unroll
    for (int i = 0; i < DD / 2; i++)
        w[i] = pack2(Wx[(2 * i) * GG + col], Wx[(2 * i + 1) * GG + col]);

    const float b = bias[col];
    const int mode = col >> 7;            // 0..4
    float wv = 0.f;
    if (mode == 1)      wv = fminf(wt1[col - 128], 0.f);
    else if (mode == 2) wv = wt[col - 256];
    else if (mode == 4) wv = wt[col - 384];   // wt[128 + (col-512)]

    const int rpb  = (NROWS + PREGRID - 1) / PREGRID;      // 886
    const int row0 = blockIdx.x * rpb;
    const int nrows = min(rpb, NROWS - row0);
    if (nrows <= 0) return;
    const int T = (nrows + RT - 1) / RT;

    // tile loader: 128 threads cp.async x (2KB), 8 threads copy td
    #define LOAD_TILE(t, buf) do {                                          \
        if (col < 128) {                                                    \
            int gr = row0 + (t) * RT + (col >> 4);                          \
            if (gr >= NROWS) gr = NROWS - 1;                                \
            cp_async16(&xs[buf][col * 4],                                   \
                       x + (size_t)gr * DD + (col & 15) * 4);               \
        } else if (col < 128 + RT) {                                        \
            int rr = col - 128;                                             \
            int gr = row0 + (t) * RT + rr;                                  \
            if (gr >= NROWS) gr = NROWS - 1;                                \
            tds[buf][rr] = td[gr];                                          \
        }                                                                   \
    } while (0)

    LOAD_TILE(0, 0);
    CP_COMMIT();

    for (int t = 0; t < T; t++) {
        if (t + 1 < T) LOAD_TILE(t + 1, (t + 1) & 1);
        CP_COMMIT();
        asm volatile("cp.async.wait_group 1;");
        __syncthreads();

        const int buf = t & 1;
        #pragma unroll
        for (int rp = 0; rp < RT / 2; rp++) {
            const ulonglong2* __restrict__ x0 =
                (const ulonglong2*)(xs[buf] + (2 * rp)     * DD);
            const ulonglong2* __restrict__ x1 =
                (const ulonglong2*)(xs[buf] + (2 * rp + 1) * DD);
            ull aA = 0, aB = 0, aC = 0, aD = 0;
            #pragma unroll
            for (int i = 0; i < DD / 4; i++) {
                ulonglong2 v0 = x0[i];
                FMA2(aA, v0.x, w[2 * i    ], aA);
                FMA2(aB, v0.y, w[2 * i + 1], aB);
                ulonglong2 v1 = x1[i];
                FMA2(aC, v1.x, w[2 * i    ], aC);
                FMA2(aD, v1.y, w[2 * i + 1], aD);
            }
            const int lr0 = t * RT + 2 * rp;
            float t0 = tds[buf][2 * rp], t1 = tds[buf][2 * rp + 1];
            float s0 = (lo2(aA) + hi2(aA)) + (lo2(aB) + hi2(aB));
            float s1 = (lo2(aC) + hi2(aC)) + (lo2(aD) + hi2(aD));
            float e0, e1;
            if (mode == 1 || mode == 2) { e0 = tanh_fast(t0 * wv); e1 = tanh_fast(t1 * wv); }
            else if (mode == 4)         { e0 = t0 * wv;            e1 = t1 * wv; }
            else                        { e0 = 0.f;                e1 = 0.f; }
            if (lr0 < nrows)
                g_pre[(size_t)(row0 + lr0) * GG + col] = s0 + b + e0;
            if (lr0 + 1 < nrows)
                g_pre[(size_t)(row0 + lr0 + 1) * GG + col] = s1 + b + e1;
        }
        __syncthreads();
    }
}

// ---------------------------------------------------------------------------
// Kernel B: sequential scan, 128 blocks x 768 threads, 2 batch rows/block.
// Rows are independent -> software-pipelined phases: in phase p, warps 0-3
// run the epilogue of row (1-r) step (p-1)/2 WHILE all warps run the matvec
// of row r=p&1 step p/2. One barrier per phase; epilogue+MUFU chain hidden.
// ---------------------------------------------------------------------------
__global__ __launch_bounds__(768, 1) void rec_kernel(
    const float* __restrict__ Wh, float* __restrict__ out)
{
    __shared__ __align__(16) float h_smem[2][HH];
    __shared__ float a_part[2][2][3 * HH];           // [row][kh][col]
    __shared__ __align__(16) float pre_buf[2][2][GG]; // [row][buf][640]

    const int tid = threadIdx.x;
    const int kh  = (tid >= 384) ? 1 : 0;
    const int col = tid - 384 * kh;
    const int b0  = blockIdx.x * 2;
    const int kbase = kh * 64;

    ull w[32];
    #pragma unroll
    for (int i = 0; i < 32; i++)
        w[i] = pack2(Wh[(kbase + 2 * i    ) * (3 * HH) + col],
                     Wh[(kbase + 2 * i + 1) * (3 * HH) + col]);

    if (tid < 2 * HH) h_smem[tid >> 7][tid & 127] = 0.f;
    float c_reg[2] = {0.f, 0.f};
    float hk[2]    = {0.f, 0.f};

    // prime groups: G_{-2}=(row0,s=0), G_{-1}=(row1,s=0)
    if (tid >= 256 && tid < 416) {
        int i = tid - 256;
        cp_async16(&pre_buf[0][0][i * 4], g_pre + (size_t)b0 * SS * GG + i * 4);
    }
    CP_COMMIT();
    if (tid >= 256 && tid < 416) {
        int i = tid - 256;
        cp_async16(&pre_buf[1][0][i * 4], g_pre + (size_t)(b0 + 1) * SS * GG + i * 4);
    }
    CP_COMMIT();
    __syncthreads();

    float* __restrict__ hseq = out;
    float* __restrict__ hT = out + (size_t)BB * SS * HH;
    float* __restrict__ cT = hT + (size_t)BB * HH;

    for (int p = 0; p <= 2 * SS; p++) {
        const int r = p & 1, s = p >> 1;

        // prefetch (r, s+1); epilogue at phase q consumes group G_{q-3},
        // guaranteed complete by the wait at phase q-1 + that phase's barrier.
        if (tid >= 256 && tid < 416) {
            int i = tid - 256;
            if (p < 2 * SS && s + 1 < SS)
                cp_async16(&pre_buf[r][(s + 1) & 1][i * 4],
                           g_pre + ((size_t)(b0 + r) * SS + (s + 1)) * GG + i * 4);
            CP_COMMIT();
            asm volatile("cp.async.wait_group 2;");
        }

        // epilogue of (row r2=1-r, step s2) — touches only row r2 state
        if (p >= 1 && tid < HH) {
            const int r2 = (p - 1) & 1, s2 = (p - 1) >> 1, j = tid;
            const float* __restrict__ pp = pre_buf[r2][s2 & 1];
            float ai  = pp[j]          + a_part[r2][0][j]          + a_part[r2][1][j];
            float pt1 = pp[HH + j];
            float pt2 = pp[2 * HH + j];
            float ac  = pp[3 * HH + j] + a_part[r2][0][HH + j]     + a_part[r2][1][HH + j];
            float ao  = pp[4 * HH + j] + a_part[r2][0][2 * HH + j] + a_part[r2][1][2 * HH + j];

            float i_t = sigm(ai);
            float t1  = sigm(pt1);
            float t2  = sigm(pt2);
            float cw  = tanh_fast(ac);
            float o_t = sigm(ao);

            float cold = c_reg[r2];
            float it1  = i_t * t1;
            float ctil = sigm((1.f - it1) * cold + it1 * cw);
            c_reg[r2]  = sigm((1.f - i_t) * cold + i_t * t2 * cw);
            float hn   = o_t + tanh_fast(ctil);

            h_smem[r2][j] = hn;
            hk[r2] = hn;
            hseq[((size_t)(b0 + r2) * SS + s2) * HH + j] = hn;
        }

        // matvec row r, step s (reads h_smem[r] written at phase p-1's epilogue)
        if (p < 2 * SS) {
            ull aA = 0, aB = 0;
            const ulonglong2* __restrict__ hp =
                (const ulonglong2*)(h_smem[r] + kbase);
            #pragma unroll
            for (int i = 0; i < 16; i++) {
                ulonglong2 v = hp[i];
                FMA2(aA, v.x, w[2 * i    ], aA);
                FMA2(aB, v.y, w[2 * i + 1], aB);
            }
            a_part[r][kh][col] = (lo2(aA) + hi2(aA)) + (lo2(aB) + hi2(aB));
        }
        __syncthreads();
    }

    if (tid < HH) {
        hT[(size_t)b0 * HH + tid]       = hk[0];
        hT[(size_t)(b0 + 1) * HH + tid] = hk[1];
        cT[(size_t)b0 * HH + tid]       = c_reg[0];
        cT[(size_t)(b0 + 1) * HH + tid] = c_reg[1];
    }
}

extern "C" void kernel_launch(void* const* d_in, const int* in_sizes, int n_in,
                              void* d_out, int out_size) {
    const float* x    = (const float*)d_in[0];
    const float* td   = (const float*)d_in[1];
    const float* Wx   = (const float*)d_in[2];
    const float* Wh   = (const float*)d_in[3];
    const float* wt1  = (const float*)d_in[4];
    const float* wt   = (const float*)d_in[5];
    const float* bias = (const float*)d_in[6];
    float* out = (float*)d_out;

    pre_kernel<<<PREGRID, 640>>>(x, td, Wx, wt1, wt, bias);
    rec_kernel<<<BB / 2, 768>>>(Wh, out);
}